// round 1
// baseline (speedup 1.0000x reference)
#include <cuda_runtime.h>
#include <math.h>

// ---------------------------------------------------------------------------
// LSForward: Born-series scattering, M=4096 pts, 4 wavenumbers (0.5m), 5 iters.
// Strategy: fully fused matrix-free matvec. Per (i,j) pair compute distance,
// one fast sincos of theta = 0.5*D, then Chebyshev recurrence generates all 4
// Green's kernels G_m = (C/D) * exp(i * m * theta). No big matrices -> no DRAM
// traffic; compute-bound on the FMA pipe.
// ---------------------------------------------------------------------------

constexpr int M_PTS  = 4096;
constexpr int NDOBS  = 64;
constexpr int NK     = 4;
constexpr int N_ITER = 5;

constexpr int TPB    = 256;                    // threads per block
constexpr int RPT    = 4;                      // rows per thread
constexpr int ROWBLK = M_PTS / (TPB * RPT);    // 4 row-blocks
constexpr int JSPLIT = 64;                     // j-partition count
constexpr int JCHUNK = M_PTS / JSPLIT;         // 64 j's per block

constexpr float C_G = 0.07957747154594767f;    // 1/(4*pi)

// Scratch (allocation-free: __device__ globals)
__device__ float g_px[M_PTS], g_py[M_PTS], g_pz[M_PTS];
__device__ float g_r2[M_PTS], g_vw[M_PTS];
__device__ float g_p0[NK * 2 * M_PTS];
__device__ float g_p [NK * 2 * M_PTS];
__device__ float g_a [NK * 2 * M_PTS];             // VW * p (matvec input)
__device__ float g_part[JSPLIT][NK * 2 * M_PTS];   // deterministic j-partials (8 MB)

// ---------------------------------------------------------------------------
// Init: split pts into SoA, r2, VW, incident wave p0 = exp(i k z), p, a.
// ---------------------------------------------------------------------------
__global__ void k_init(const float* __restrict__ V,
                       const float* __restrict__ pts,
                       const float* __restrict__ w) {
    int i = blockIdx.x * blockDim.x + threadIdx.x;
    if (i >= M_PTS) return;
    float x = pts[3 * i], y = pts[3 * i + 1], z = pts[3 * i + 2];
    g_px[i] = x; g_py[i] = y; g_pz[i] = z;
    g_r2[i] = x * x + y * y + z * z;
    float vw = V[i] * w[i];
    g_vw[i] = vw;
    float dd = z;  // incident dir = (0,0,1)
#pragma unroll
    for (int m = 0; m < NK; m++) {
        float kv = 0.5f * (float)(m + 1);
        float s, c;
        sincosf(kv * dd, &s, &c);   // accurate version in the cheap kernel
        g_p0[m * 2 * M_PTS + i]          = c;
        g_p0[m * 2 * M_PTS + M_PTS + i]  = s;
        g_p [m * 2 * M_PTS + i]          = c;
        g_p [m * 2 * M_PTS + M_PTS + i]  = s;
        g_a [m * 2 * M_PTS + i]          = vw * c;
        g_a [m * 2 * M_PTS + M_PTS + i]  = vw * s;
    }
}

// ---------------------------------------------------------------------------
// Core: one Born matvec over a (1024-row x 64-j) tile per block.
// grid = (ROWBLK, JSPLIT). Each thread owns 4 rows (strided by TPB) so the
// per-j shared loads amortize 4x.
// ---------------------------------------------------------------------------
__global__ __launch_bounds__(TPB) void k_acc() {
    __shared__ alignas(16) float sj[JCHUNK][12];  // px,py,pz,r2, ar0,ai0,...,ar3,ai3

    int t  = threadIdx.x;
    int j0 = blockIdx.y * JCHUNK;

    if (t < JCHUNK) {
        int j = j0 + t;
        sj[t][0] = g_px[j];
        sj[t][1] = g_py[j];
        sj[t][2] = g_pz[j];
        sj[t][3] = g_r2[j];
#pragma unroll
        for (int m = 0; m < NK; m++) {
            sj[t][4 + 2 * m] = g_a[m * 2 * M_PTS + j];
            sj[t][5 + 2 * m] = g_a[m * 2 * M_PTS + M_PTS + j];
        }
    }
    __syncthreads();

    int rbase = blockIdx.x * (TPB * RPT) + t;
    float pix[RPT], piy[RPT], piz[RPT], r2i[RPT];
#pragma unroll
    for (int r = 0; r < RPT; r++) {
        int row = rbase + r * TPB;
        pix[r] = g_px[row]; piy[r] = g_py[row];
        piz[r] = g_pz[row]; r2i[r] = g_r2[row];
    }

    float accr[RPT][NK], acci[RPT][NK];
#pragma unroll
    for (int r = 0; r < RPT; r++)
#pragma unroll
        for (int m = 0; m < NK; m++) { accr[r][m] = 0.f; acci[r][m] = 0.f; }

#pragma unroll 1
    for (int jj = 0; jj < JCHUNK; jj++) {
        float4 P  = *reinterpret_cast<const float4*>(&sj[jj][0]);
        float4 A0 = *reinterpret_cast<const float4*>(&sj[jj][4]);
        float4 A1 = *reinterpret_cast<const float4*>(&sj[jj][8]);
        int jg = j0 + jj;
#pragma unroll
        for (int r = 0; r < RPT; r++) {
            int row = rbase + r * TPB;
            float dot = fmaf(pix[r], P.x, fmaf(piy[r], P.y, piz[r] * P.z));
            float d2  = fmaf(-2.f, dot, r2i[r] + P.w);
            d2 = fmaxf(d2, 1e-12f);
            float rinv = rsqrtf(d2);
            float D    = d2 * rinv;
            float sc   = (row == jg) ? 0.f : C_G * rinv;
            float s1, c1;
            __sincosf(0.5f * D, &s1, &c1);       // theta = 0.5*D; k_m = 0.5*m
            float tc  = c1 + c1;
            // Chebyshev: G_m = sc * exp(i m theta), G_{m+1} = tc*G_m - G_{m-1}
            float g1r = sc * c1,             g1i = sc * s1;
            float g2r = fmaf(tc, g1r, -sc);  float g2i = tc * g1i;
            float g3r = fmaf(tc, g2r, -g1r); float g3i = fmaf(tc, g2i, -g1i);
            float g4r = fmaf(tc, g3r, -g2r); float g4i = fmaf(tc, g3i, -g2i);
            // complex matvec accumulate for each k
            accr[r][0] = fmaf(g1r, A0.x, fmaf(-g1i, A0.y, accr[r][0]));
            acci[r][0] = fmaf(g1r, A0.y, fmaf( g1i, A0.x, acci[r][0]));
            accr[r][1] = fmaf(g2r, A0.z, fmaf(-g2i, A0.w, accr[r][1]));
            acci[r][1] = fmaf(g2r, A0.w, fmaf( g2i, A0.z, acci[r][1]));
            accr[r][2] = fmaf(g3r, A1.x, fmaf(-g3i, A1.y, accr[r][2]));
            acci[r][2] = fmaf(g3r, A1.y, fmaf( g3i, A1.x, acci[r][2]));
            accr[r][3] = fmaf(g4r, A1.z, fmaf(-g4i, A1.w, accr[r][3]));
            acci[r][3] = fmaf(g4r, A1.w, fmaf( g4i, A1.z, acci[r][3]));
        }
    }

    float* part = g_part[blockIdx.y];
#pragma unroll
    for (int r = 0; r < RPT; r++) {
        int row = rbase + r * TPB;
#pragma unroll
        for (int m = 0; m < NK; m++) {
            part[m * 2 * M_PTS + row]         = accr[r][m];
            part[m * 2 * M_PTS + M_PTS + row] = acci[r][m];
        }
    }
}

// ---------------------------------------------------------------------------
// Deterministic partial reduction + Born update: p = p0 + sum; a = VW*p.
// ---------------------------------------------------------------------------
__global__ void k_update() {
    int e = blockIdx.x * blockDim.x + threadIdx.x;  // 0 .. NK*2*M-1
    float s = 0.f;
#pragma unroll 8
    for (int js = 0; js < JSPLIT; js++) s += g_part[js][e];
    float pv = g_p0[e] + s;
    g_p[e] = pv;
    g_a[e] = g_vw[e & (M_PTS - 1)] * pv;
}

// ---------------------------------------------------------------------------
// Far-field: one block per observation direction, 4 k's via same recurrence.
// out[m][d][{re,im}] = -C * sum_j w_j * (V_j p_j) * exp(-i k pts_j.obs_d)
// ---------------------------------------------------------------------------
__global__ __launch_bounds__(TPB) void k_far(const float* __restrict__ V,
                                             const float* __restrict__ obs,
                                             const float* __restrict__ w,
                                             float* __restrict__ out) {
    int d = blockIdx.x;
    int t = threadIdx.x;
    float ox = obs[3 * d], oy = obs[3 * d + 1], oz = obs[3 * d + 2];

    float fr[NK] = {0.f, 0.f, 0.f, 0.f};
    float fi[NK] = {0.f, 0.f, 0.f, 0.f};

    for (int j = t; j < M_PTS; j += TPB) {
        float q = fmaf(g_px[j], ox, fmaf(g_py[j], oy, g_pz[j] * oz));
        float s1, c1;
        __sincosf(0.5f * q, &s1, &c1);
        float tc = c1 + c1;
        float cm[NK], sm[NK];
        cm[0] = c1;                      sm[0] = s1;
        cm[1] = fmaf(tc, c1, -1.f);      sm[1] = tc * s1;
        cm[2] = fmaf(tc, cm[1], -cm[0]); sm[2] = fmaf(tc, sm[1], -sm[0]);
        cm[3] = fmaf(tc, cm[2], -cm[1]); sm[3] = fmaf(tc, sm[2], -sm[1]);
        float v = V[j], wj = w[j];
#pragma unroll
        for (int m = 0; m < NK; m++) {
            float pr = g_p[m * 2 * M_PTS + j];
            float pi = g_p[m * 2 * M_PTS + M_PTS + j];
            float zr = v * pr, zi = v * pi;
            // exp(-ikQ): re = cos(kQ), im = -sin(kQ)
            float ir = fmaf(zr, cm[m],  zi * sm[m]);
            float ii = fmaf(zi, cm[m], -zr * sm[m]);
            fr[m] = fmaf(wj, ir, fr[m]);
            fi[m] = fmaf(wj, ii, fi[m]);
        }
    }

    // warp reduce, then cross-warp via smem
#pragma unroll
    for (int off = 16; off; off >>= 1) {
#pragma unroll
        for (int m = 0; m < NK; m++) {
            fr[m] += __shfl_down_sync(0xffffffffu, fr[m], off);
            fi[m] += __shfl_down_sync(0xffffffffu, fi[m], off);
        }
    }
    __shared__ float sred[8][TPB / 32];
    int lane = t & 31, wid = t >> 5;
    if (lane == 0) {
#pragma unroll
        for (int m = 0; m < NK; m++) {
            sred[2 * m][wid]     = fr[m];
            sred[2 * m + 1][wid] = fi[m];
        }
    }
    __syncthreads();
    if (t < 8) {
        float s = 0.f;
#pragma unroll
        for (int wdx = 0; wdx < TPB / 32; wdx++) s += sred[t][wdx];
        int m = t >> 1, c = t & 1;
        out[m * NDOBS * 2 + d * 2 + c] = -C_G * s;
    }
}

// ---------------------------------------------------------------------------
extern "C" void kernel_launch(void* const* d_in, const int* in_sizes, int n_in,
                              void* d_out, int out_size) {
    const float* V   = (const float*)d_in[0];   // [4096]
    const float* obs = (const float*)d_in[1];   // [64,3]
    const float* pts = (const float*)d_in[2];   // [4096,3]
    const float* w   = (const float*)d_in[3];   // [4096]
    float* out = (float*)d_out;                 // [4,64,2]

    k_init<<<M_PTS / TPB, TPB>>>(V, pts, w);
    for (int it = 0; it < N_ITER; it++) {
        k_acc<<<dim3(ROWBLK, JSPLIT), TPB>>>();
        k_update<<<(NK * 2 * M_PTS) / TPB, TPB>>>();
    }
    k_far<<<NDOBS, TPB>>>(V, obs, w, out);
}